// round 5
// baseline (speedup 1.0000x reference)
#include <cuda_runtime.h>
#include <cuda_fp16.h>
#include <mma.h>
#include <cstdint>

using namespace nvcuda;

// ---------------- problem constants ----------------
#define BB 16
#define EE 8
#define CC 1024
#define DD 512
#define FF 2048

// ---------------- tiling ----------------
#define BM 128
#define BN 256
#define BK 64
#define KS 72                          // smem row stride in halfs (144B): 16B-aligned, LDSM conflict-free
#define A_ROWS BM
#define B_ROWS BN
#define STAGE_ELEMS ((A_ROWS + B_ROWS) * KS)     // 27648
#define STAGE_BYTES (STAGE_ELEMS * 2)            // 55296
#define NSTAGE 3
#define SMEM_TOTAL (NSTAGE * STAGE_BYTES)        // 165888
#define EPI_LD (BN + 4)                // f32 epilogue staging stride (260)

// ---------------- scratch (device globals; no allocs) ----------------
__device__ __half g_Xh [(size_t)BB * EE * CC * DD];      // X  fp16
__device__ __half g_W1t[(size_t)EE * FF * DD];           // W1^T [e][n=F][k=D] fp16
__device__ __half g_W2t[(size_t)EE * DD * FF];           // W2^T [e][n=D][k=F] fp16
__device__ __half g_Hh [(size_t)BB * EE * CC * FF];      // H  fp16

// ---------------- PTX helpers ----------------
__device__ __forceinline__ uint32_t smem_u32(const void* p) {
    uint32_t a;
    asm("{ .reg .u64 t; cvta.to.shared.u64 t, %1; cvt.u32.u64 %0, t; }" : "=r"(a) : "l"(p));
    return a;
}
#define CP_ASYNC16(dst, src) \
    asm volatile("cp.async.cg.shared.global [%0], [%1], 16;" :: "r"(dst), "l"(src) : "memory")
#define CP_COMMIT()  asm volatile("cp.async.commit_group;" ::: "memory")
#define CP_WAIT1()   asm volatile("cp.async.wait_group 1;" ::: "memory")

// ---------------- math helpers ----------------
__device__ __forceinline__ float gelu_fast(float x) {
    // tanh-gelu via ex2.approx: tanh(u) = 1 - 2/(1 + e^{2u})
    float u = 0.7978845608028654f * fmaf(0.044715f * x, x * x, x);
    float y = 2.8853900817779268f * u;     // 2u / ln2
    float z;
    asm("ex2.approx.f32 %0, %1;" : "=f"(z) : "f"(y));
    float t = 1.0f - __fdividef(2.0f, z + 1.0f);
    return 0.5f * x * (1.0f + t);
}

// ---------------- prepass: fp32 -> fp16 (coalesced) ----------------
__global__ void to_fp16(const float* __restrict__ src, __half* __restrict__ dst, size_t n4) {
    size_t i = blockIdx.x * (size_t)blockDim.x + threadIdx.x;
    if (i >= n4) return;
    float4 v = reinterpret_cast<const float4*>(src)[i];
    __half2 h0 = __floats2half2_rn(v.x, v.y);
    __half2 h1 = __floats2half2_rn(v.z, v.w);
    uint2 u;
    u.x = *reinterpret_cast<unsigned*>(&h0);
    u.y = *reinterpret_cast<unsigned*>(&h1);
    reinterpret_cast<uint2*>(dst)[i] = u;
}

// ---------------- prepass: tiled transpose  w[e][K][N] -> t[e][N][K] fp16 ----------------
__global__ void transpose_fp16(const float* __restrict__ w, __half* __restrict__ t,
                               int K, int N) {
    __shared__ float tile[32][33];
    const int e = blockIdx.z;
    const int k0 = blockIdx.y * 32;
    const int n0 = blockIdx.x * 32;
    const float* we = w + (size_t)e * K * N;
#pragma unroll
    for (int i = 0; i < 4; i++) {
        int k = k0 + threadIdx.y + i * 8;
        tile[threadIdx.y + i * 8][threadIdx.x] = we[(size_t)k * N + n0 + threadIdx.x];
    }
    __syncthreads();
    __half* te = t + (size_t)e * N * K;
#pragma unroll
    for (int i = 0; i < 4; i++) {
        int n = n0 + threadIdx.y + i * 8;
        te[(size_t)n * K + k0 + threadIdx.x] = __float2half_rn(tile[threadIdx.x][threadIdx.y + i * 8]);
    }
}

// ---------------- main grouped GEMM (fp16 mma, cp.async 3-stage, 128x256 CTA tile) ----------------
// C[128x256] = A[128xK] @ B[256xK]^T + bias ; mode0: gelu -> Oh (fp16) ; mode1: -> outF (fp32)
__global__ void __launch_bounds__(256)
moe_gemm(const __half* __restrict__ Ah, const __half* __restrict__ Bh,
         const float* __restrict__ bias,
         float* __restrict__ outF, __half* __restrict__ Oh,
         int K, int Ntot, int mode)
{
    extern __shared__ char smc[];
    const uint32_t sbase = smem_u32(smc);
    const int tid = threadIdx.x;
    const int wid = tid >> 5;

    const int g = blockIdx.z;
    const int e = g & (EE - 1);
    const int mBase = blockIdx.y * BM;
    const int nBase = blockIdx.x * BN;

    const __half* aP = Ah + (size_t)g * CC * K + (size_t)mBase * K;
    const __half* bP = Bh + (size_t)e * Ntot * K + (size_t)nBase * K;

    const int KT = K / BK;

    // stage loader: A 128 rows + B 256 rows, each 128B wide (12 cp.async16 / thread)
    auto loadStage = [&](int kt) {
        const int k0 = kt * BK;
        const uint32_t s = sbase + (uint32_t)((kt % NSTAGE) * STAGE_BYTES);
#pragma unroll
        for (int i = 0; i < 4; i++) {            // A: 1024 chunks
            int idx = tid + i * 256;
            int row = idx >> 3, q = idx & 7;
            CP_ASYNC16(s + (uint32_t)(row * (KS * 2) + q * 16),
                       aP + (size_t)row * K + k0 + q * 8);
        }
        const uint32_t sb = s + A_ROWS * KS * 2;
#pragma unroll
        for (int i = 0; i < 8; i++) {            // B: 2048 chunks
            int idx = tid + i * 256;
            int row = idx >> 3, q = idx & 7;
            CP_ASYNC16(sb + (uint32_t)(row * (KS * 2) + q * 16),
                       bP + (size_t)row * K + k0 + q * 8);
        }
    };

    // warp tile 64x64: warp grid 2 (M) x 4 (N)
    const int wm = (wid & 1) * 64;
    const int wn = (wid >> 1) * 64;

    wmma::fragment<wmma::accumulator, 16, 16, 16, float> acc[4][4];
#pragma unroll
    for (int mi = 0; mi < 4; mi++)
#pragma unroll
        for (int ni = 0; ni < 4; ni++)
            wmma::fill_fragment(acc[mi][ni], 0.0f);

    loadStage(0); CP_COMMIT();
    loadStage(1); CP_COMMIT();

    for (int kt = 0; kt < KT; kt++) {
        CP_WAIT1();                    // stage kt complete
        __syncthreads();               // visibility + all threads done with stage kt-1's slot
        if (kt + 2 < KT) loadStage(kt + 2);
        CP_COMMIT();                   // unconditional: uniform group accounting

        const __half* sA = (const __half*)(smc + (kt % NSTAGE) * STAGE_BYTES);
        const __half* sB = sA + A_ROWS * KS;

#pragma unroll
        for (int ks = 0; ks < 4; ks++) {
            wmma::fragment<wmma::matrix_a, 16, 16, 16, __half, wmma::row_major> fa[4];
            wmma::fragment<wmma::matrix_b, 16, 16, 16, __half, wmma::col_major> fb[4];
#pragma unroll
            for (int mi = 0; mi < 4; mi++)
                wmma::load_matrix_sync(fa[mi], sA + (wm + mi * 16) * KS + ks * 16, KS);
#pragma unroll
            for (int ni = 0; ni < 4; ni++)
                wmma::load_matrix_sync(fb[ni], sB + (wn + ni * 16) * KS + ks * 16, KS);
#pragma unroll
            for (int mi = 0; mi < 4; mi++)
#pragma unroll
                for (int ni = 0; ni < 4; ni++)
                    wmma::mma_sync(acc[mi][ni], fa[mi], fb[ni], acc[mi][ni]);
        }
    }

    // ---- epilogue: stage f32 in smem, bias (+gelu), vectorized stores ----
    __syncthreads();
    float* stage = reinterpret_cast<float*>(smc);
#pragma unroll
    for (int mi = 0; mi < 4; mi++)
#pragma unroll
        for (int ni = 0; ni < 4; ni++)
            wmma::store_matrix_sync(&stage[(wm + mi * 16) * EPI_LD + wn + ni * 16],
                                    acc[mi][ni], EPI_LD, wmma::mem_row_major);
    __syncthreads();

#pragma unroll
    for (int i = 0; i < 32; i++) {
        int idx = tid + i * 256;          // float4 index, 0..8191
        int row = idx >> 6;               // 64 float4 per row of 256
        int c4 = idx & 63;
        float4 v = *reinterpret_cast<float4*>(&stage[row * EPI_LD + c4 * 4]);
        int n = nBase + c4 * 4;
        v.x += bias[n + 0]; v.y += bias[n + 1]; v.z += bias[n + 2]; v.w += bias[n + 3];
        size_t off = (size_t)g * CC * Ntot + (size_t)(mBase + row) * Ntot + n;
        if (mode == 0) {
            __half2 h0 = __floats2half2_rn(gelu_fast(v.x), gelu_fast(v.y));
            __half2 h1 = __floats2half2_rn(gelu_fast(v.z), gelu_fast(v.w));
            uint2 u;
            u.x = *reinterpret_cast<unsigned*>(&h0);
            u.y = *reinterpret_cast<unsigned*>(&h1);
            *reinterpret_cast<uint2*>(Oh + off) = u;
        } else {
            *reinterpret_cast<float4*>(outF + off) = v;
        }
    }
}

// ---------------- host launcher ----------------
extern "C" void kernel_launch(void* const* d_in, const int* in_sizes, int n_in,
                              void* d_out, int out_size) {
    const float* inputs = (const float*)d_in[0];   // [B, E*C, D]
    const float* w1     = (const float*)d_in[1];   // [E, D, F]
    const float* b1     = (const float*)d_in[2];   // [E, F]
    const float* w2     = (const float*)d_in[3];   // [E, F, D]
    const float* b2     = (const float*)d_in[4];   // [E, D]
    float*       out    = (float*)d_out;           // [B, E*C, D]

    void *xh, *w1t, *w2t, *hh;
    cudaGetSymbolAddress(&xh, g_Xh);
    cudaGetSymbolAddress(&w1t, g_W1t);
    cudaGetSymbolAddress(&w2t, g_W2t);
    cudaGetSymbolAddress(&hh, g_Hh);

    cudaFuncSetAttribute(moe_gemm, cudaFuncAttributeMaxDynamicSharedMemorySize, SMEM_TOTAL);

    // prepass
    {
        size_t n4 = (size_t)BB * EE * CC * DD / 4;
        to_fp16<<<(unsigned)((n4 + 255) / 256), 256>>>(inputs, (__half*)xh, n4);
    }
    {
        dim3 blk(32, 8);
        dim3 g1(FF / 32, DD / 32, EE);
        transpose_fp16<<<g1, blk>>>(w1, (__half*)w1t, DD, FF);
        dim3 g2(DD / 32, FF / 32, EE);
        transpose_fp16<<<g2, blk>>>(w2, (__half*)w2t, FF, DD);
    }

    // GEMM1: H = gelu(X @ W1 + b1): per group M=1024, K=512, N=2048
    {
        dim3 grid(FF / BN, CC / BM, BB * EE);
        moe_gemm<<<grid, 256, SMEM_TOTAL>>>(
            (const __half*)xh, (const __half*)w1t, b1,
            nullptr, (__half*)hh, DD, FF, 0);
    }
    // GEMM2: Y = H @ W2 + b2: per group M=1024, K=2048, N=512
    {
        dim3 grid(DD / BN, CC / BM, BB * EE);
        moe_gemm<<<grid, 256, SMEM_TOTAL>>>(
            (const __half*)hh, (const __half*)w2t, b2,
            out, nullptr, FF, DD, 1);
    }
}

// round 6
// speedup vs baseline: 1.1366x; 1.1366x over previous
#include <cuda_runtime.h>
#include <cuda_fp16.h>
#include <mma.h>
#include <cstdint>

using namespace nvcuda;

// ---------------- problem constants ----------------
#define BB 16
#define EE 8
#define CC 1024
#define DD 512
#define FF 2048

// ---------------- tiling ----------------
#define BM 128
#define BN 128
#define BK 64
#define KS 72                          // smem row stride in halfs (144B): 16B-aligned, conflict-free
#define A_ROWS BM
#define B_ROWS BN
#define STAGE_ELEMS ((A_ROWS + B_ROWS) * KS)     // 18432
#define STAGE_BYTES (STAGE_ELEMS * 2)            // 36864
#define NSTAGE 3
#define SMEM_TOTAL (NSTAGE * STAGE_BYTES)        // 110592 -> 2 CTAs/SM
#define EPI_LD (BN + 4)                          // f32 epilogue staging stride (132)
#define NTHREADS 128

// ---------------- scratch (device globals; no allocs) ----------------
__device__ __half g_Xh [(size_t)BB * EE * CC * DD];      // X  fp16
__device__ __half g_W1t[(size_t)EE * FF * DD];           // W1^T [e][n=F][k=D] fp16
__device__ __half g_W2t[(size_t)EE * DD * FF];           // W2^T [e][n=D][k=F] fp16
__device__ __half g_Hh [(size_t)BB * EE * CC * FF];      // H  fp16

// ---------------- PTX helpers ----------------
__device__ __forceinline__ uint32_t smem_u32(const void* p) {
    uint32_t a;
    asm("{ .reg .u64 t; cvta.to.shared.u64 t, %1; cvt.u32.u64 %0, t; }" : "=r"(a) : "l"(p));
    return a;
}
#define CP_ASYNC16(dst, src) \
    asm volatile("cp.async.cg.shared.global [%0], [%1], 16;" :: "r"(dst), "l"(src) : "memory")
#define CP_COMMIT()  asm volatile("cp.async.commit_group;" ::: "memory")
#define CP_WAIT1()   asm volatile("cp.async.wait_group 1;" ::: "memory")

// ---------------- math helpers ----------------
__device__ __forceinline__ float gelu_fast(float x) {
    float u = 0.7978845608028654f * fmaf(0.044715f * x, x * x, x);
    float y = 2.8853900817779268f * u;     // 2u / ln2
    float z;
    asm("ex2.approx.f32 %0, %1;" : "=f"(z) : "f"(y));
    float t = 1.0f - __fdividef(2.0f, z + 1.0f);
    return 0.5f * x * (1.0f + t);
}

// ---------------- prepass: fp32 -> fp16 (coalesced) ----------------
__global__ void to_fp16(const float* __restrict__ src, __half* __restrict__ dst, size_t n4) {
    size_t i = blockIdx.x * (size_t)blockDim.x + threadIdx.x;
    if (i >= n4) return;
    float4 v = reinterpret_cast<const float4*>(src)[i];
    __half2 h0 = __floats2half2_rn(v.x, v.y);
    __half2 h1 = __floats2half2_rn(v.z, v.w);
    uint2 u;
    u.x = *reinterpret_cast<unsigned*>(&h0);
    u.y = *reinterpret_cast<unsigned*>(&h1);
    reinterpret_cast<uint2*>(dst)[i] = u;
}

// ---------------- prepass: tiled transpose  w[e][K][N] -> t[e][N][K] fp16 ----------------
__global__ void transpose_fp16(const float* __restrict__ w, __half* __restrict__ t,
                               int K, int N) {
    __shared__ float tile[32][33];
    const int e = blockIdx.z;
    const int k0 = blockIdx.y * 32;
    const int n0 = blockIdx.x * 32;
    const float* we = w + (size_t)e * K * N;
#pragma unroll
    for (int i = 0; i < 4; i++) {
        int k = k0 + threadIdx.y + i * 8;
        tile[threadIdx.y + i * 8][threadIdx.x] = we[(size_t)k * N + n0 + threadIdx.x];
    }
    __syncthreads();
    __half* te = t + (size_t)e * N * K;
#pragma unroll
    for (int i = 0; i < 4; i++) {
        int n = n0 + threadIdx.y + i * 8;
        te[(size_t)n * K + k0 + threadIdx.x] = __float2half_rn(tile[threadIdx.x][threadIdx.y + i * 8]);
    }
}

// ---------------- main grouped GEMM ----------------
// 128 threads, 4 warps, warp tile 64x64, CTA tile 128x128, cp.async 3-stage.
// C = A[128xK] @ B[128xK]^T + bias ; mode0: gelu -> Oh (fp16) ; mode1: -> outF (fp32)
__global__ void __launch_bounds__(NTHREADS)
moe_gemm(const __half* __restrict__ Ah, const __half* __restrict__ Bh,
         const float* __restrict__ bias,
         float* __restrict__ outF, __half* __restrict__ Oh,
         int K, int Ntot, int mode)
{
    extern __shared__ char smc[];
    const uint32_t sbase = smem_u32(smc);
    const int tid = threadIdx.x;
    const int wid = tid >> 5;

    const int g = blockIdx.z;
    const int e = g & (EE - 1);
    const int mBase = blockIdx.y * BM;
    const int nBase = blockIdx.x * BN;

    const __half* aP = Ah + (size_t)g * CC * K + (size_t)mBase * K;
    const __half* bP = Bh + (size_t)e * Ntot * K + (size_t)nBase * K;

    const int KT = K / BK;

    // stage loader: 256 rows x 128B = 2304 x 16B chunks, 18 per thread
    auto loadStage = [&](int kt) {
        const int k0 = kt * BK;
        const uint32_t s = sbase + (uint32_t)((kt % NSTAGE) * STAGE_BYTES);
#pragma unroll
        for (int i = 0; i < 8; i++) {            // A+B rows 0..127 (first 128 rows = A)
            int idx = tid + i * NTHREADS;        // 0..1023
            int row = idx >> 3, q = idx & 7;
            CP_ASYNC16(s + (uint32_t)(row * (KS * 2) + q * 16),
                       aP + (size_t)row * K + k0 + q * 8);
        }
        const uint32_t sb = s + A_ROWS * KS * 2;
#pragma unroll
        for (int i = 0; i < 8; i++) {            // B rows 0..127
            int idx = tid + i * NTHREADS;
            int row = idx >> 3, q = idx & 7;
            CP_ASYNC16(sb + (uint32_t)(row * (KS * 2) + q * 16),
                       bP + (size_t)row * K + k0 + q * 8);
        }
    };

    // warp grid 2(M) x 2(N); warp tile 64x64
    const int wm = (wid & 1) * 64;
    const int wn = (wid >> 1) * 64;

    wmma::fragment<wmma::accumulator, 16, 16, 16, float> acc[4][4];
#pragma unroll
    for (int mi = 0; mi < 4; mi++)
#pragma unroll
        for (int ni = 0; ni < 4; ni++)
            wmma::fill_fragment(acc[mi][ni], 0.0f);

    loadStage(0); CP_COMMIT();
    loadStage(1); CP_COMMIT();

    for (int kt = 0; kt < KT; kt++) {
        CP_WAIT1();                    // stage kt landed
        __syncthreads();               // visibility + stage slot reuse safety
        if (kt + 2 < KT) loadStage(kt + 2);
        CP_COMMIT();                   // unconditional: uniform group accounting

        const __half* sA = (const __half*)(smc + (kt % NSTAGE) * STAGE_BYTES);
        const __half* sB = sA + A_ROWS * KS;

#pragma unroll
        for (int ks = 0; ks < 4; ks++) {
            // keep fb resident across the mi loop; stream fa
            wmma::fragment<wmma::matrix_b, 16, 16, 16, __half, wmma::col_major> fb[4];
#pragma unroll
            for (int ni = 0; ni < 4; ni++)
                wmma::load_matrix_sync(fb[ni], sB + (wn + ni * 16) * KS + ks * 16, KS);
#pragma unroll
            for (int mi = 0; mi < 4; mi++) {
                wmma::fragment<wmma::matrix_a, 16, 16, 16, __half, wmma::row_major> fa;
                wmma::load_matrix_sync(fa, sA + (wm + mi * 16) * KS + ks * 16, KS);
#pragma unroll
                for (int ni = 0; ni < 4; ni++)
                    wmma::mma_sync(acc[mi][ni], fa, fb[ni], acc[mi][ni]);
            }
        }
    }

    // ---- epilogue: stage f32 in smem, bias (+gelu), vectorized stores ----
    __syncthreads();
    float* stage = reinterpret_cast<float*>(smc);
#pragma unroll
    for (int mi = 0; mi < 4; mi++)
#pragma unroll
        for (int ni = 0; ni < 4; ni++)
            wmma::store_matrix_sync(&stage[(wm + mi * 16) * EPI_LD + wn + ni * 16],
                                    acc[mi][ni], EPI_LD, wmma::mem_row_major);
    __syncthreads();

#pragma unroll
    for (int i = 0; i < 32; i++) {
        int idx = tid + i * NTHREADS;     // float4 index, 0..4095
        int row = idx >> 5;               // 32 float4 per row of 128
        int c4 = idx & 31;
        float4 v = *reinterpret_cast<float4*>(&stage[row * EPI_LD + c4 * 4]);
        int n = nBase + c4 * 4;
        v.x += __ldg(bias + n + 0); v.y += __ldg(bias + n + 1);
        v.z += __ldg(bias + n + 2); v.w += __ldg(bias + n + 3);
        size_t off = (size_t)g * CC * Ntot + (size_t)(mBase + row) * Ntot + n;
        if (mode == 0) {
            __half2 h0 = __floats2half2_rn(gelu_fast(v.x), gelu_fast(v.y));
            __half2 h1 = __floats2half2_rn(gelu_fast(v.z), gelu_fast(v.w));
            uint2 u;
            u.x = *reinterpret_cast<unsigned*>(&h0);
            u.y = *reinterpret_cast<unsigned*>(&h1);
            *reinterpret_cast<uint2*>(Oh + off) = u;
        } else {
            *reinterpret_cast<float4*>(outF + off) = v;
        }
    }
}

// ---------------- host launcher ----------------
extern "C" void kernel_launch(void* const* d_in, const int* in_sizes, int n_in,
                              void* d_out, int out_size) {
    const float* inputs = (const float*)d_in[0];   // [B, E*C, D]
    const float* w1     = (const float*)d_in[1];   // [E, D, F]
    const float* b1     = (const float*)d_in[2];   // [E, F]
    const float* w2     = (const float*)d_in[3];   // [E, F, D]
    const float* b2     = (const float*)d_in[4];   // [E, D]
    float*       out    = (float*)d_out;           // [B, E*C, D]

    void *xh, *w1t, *w2t, *hh;
    cudaGetSymbolAddress(&xh, g_Xh);
    cudaGetSymbolAddress(&w1t, g_W1t);
    cudaGetSymbolAddress(&w2t, g_W2t);
    cudaGetSymbolAddress(&hh, g_Hh);

    cudaFuncSetAttribute(moe_gemm, cudaFuncAttributeMaxDynamicSharedMemorySize, SMEM_TOTAL);

    // prepass
    {
        size_t n4 = (size_t)BB * EE * CC * DD / 4;
        to_fp16<<<(unsigned)((n4 + 255) / 256), 256>>>(inputs, (__half*)xh, n4);
    }
    {
        dim3 blk(32, 8);
        dim3 g1(FF / 32, DD / 32, EE);
        transpose_fp16<<<g1, blk>>>(w1, (__half*)w1t, DD, FF);
        dim3 g2(DD / 32, FF / 32, EE);
        transpose_fp16<<<g2, blk>>>(w2, (__half*)w2t, FF, DD);
    }

    // GEMM1: H = gelu(X @ W1 + b1): per group M=1024, K=512, N=2048
    {
        dim3 grid(FF / BN, CC / BM, BB * EE);
        moe_gemm<<<grid, NTHREADS, SMEM_TOTAL>>>(
            (const __half*)xh, (const __half*)w1t, b1,
            nullptr, (__half*)hh, DD, FF, 0);
    }
    // GEMM2: Y = H @ W2 + b2: per group M=1024, K=2048, N=512
    {
        dim3 grid(DD / BN, CC / BM, BB * EE);
        moe_gemm<<<grid, NTHREADS, SMEM_TOTAL>>>(
            (const __half*)hh, (const __half*)w2t, b2,
            out, nullptr, FF, DD, 1);
    }
}